// round 15
// baseline (speedup 1.0000x reference)
#include <cuda_runtime.h>
#include <cuda_fp16.h>
#include <math.h>

#define BB 16
#define CC 64
#define HH 144
#define WW 144
#define hs 48
#define wsz 48
#define G9 9
#define C9 576
#define HW (hs*wsz)          // 2304
#define NPIX 36864.0f        // B*h*w
#define EPSV 1e-5f

typedef unsigned long long ull;
typedef unsigned int uint32;

// ---- packed f32x2 helpers (sm_103a FFMA2 path) ----
__device__ __forceinline__ ull ffma2(ull a, ull b, ull c) {
    ull d; asm("fma.rn.f32x2 %0, %1, %2, %3;" : "=l"(d) : "l"(a), "l"(b), "l"(c)); return d;
}
__device__ __forceinline__ ull add2(ull a, ull b) {
    ull d; asm("add.rn.f32x2 %0, %1, %2;" : "=l"(d) : "l"(a), "l"(b)); return d;
}
__device__ __forceinline__ void unpack2(ull v, float& lo, float& hi) {
    asm("mov.b64 {%0, %1}, %2;" : "=f"(lo), "=f"(hi) : "l"(v));
}
__device__ __forceinline__ uint32 f2tf32(float f) {
    uint32 r; asm("cvt.rna.tf32.f32 %0, %1;" : "=r"(r) : "f"(f)); return r;
}
__device__ __forceinline__ void mma_tf32(float c[4], uint32 a0, uint32 a1, uint32 a2, uint32 a3,
                                         uint32 b0, uint32 b1) {
    asm("mma.sync.aligned.m16n8k8.row.col.f32.tf32.tf32.f32 "
        "{%0,%1,%2,%3}, {%4,%5,%6,%7}, {%8,%9}, {%0,%1,%2,%3};"
        : "+f"(c[0]), "+f"(c[1]), "+f"(c[2]), "+f"(c[3])
        : "r"(a0), "r"(a1), "r"(a2), "r"(a3), "r"(b0), "r"(b1));
}

// ---- static scratch ----
__device__ __align__(16) __half g_mixed[BB*C9*HW];   // 42.5 MB
__device__ __align__(16) __half g_s[BB*CC*HW];       // 4.7 MB (fp16 now)
__device__ float  g_sum1[C9], g_sq1[C9];
__device__ float  g_sum2[CC], g_sq2[CC];

// ---------------------------------------------------------------
// K0: zero BN accumulators.
// ---------------------------------------------------------------
__global__ void k_zero() {
    int i = threadIdx.x;
    if (i < C9) { g_sum1[i] = 0.f; g_sq1[i] = 0.f; }
    if (i < CC) { g_sum2[i] = 0.f; g_sq2[i] = 0.f; }
}

// ---------------------------------------------------------------
// K1: FUSED maxpool3x3 + focus + mixer GEMM (tf32 tensor cores).
// Block = (focus row hh, batch b), 256 threads (8 warps).
// Dynamic smem (92160 B -> 2 blocks/SM):
//   vm[3]: 64ch x 144 fp16 vertical 3-max planes   3 x 18432 B
//   Xs[2]: 64k x 72 tf32 pooled X tile (dbl buf)   2 x 18432 B
// A-fragments (mixer weights) live in registers, loaded from
// global (L2-hot) during each group's build phase.
// ONE barrier per group: build Xs[g&1] -> sync -> MMA.
//   (hazard-free: build(g) only after sync(g-1), by which point
//    every warp finished MMA(g-2) on the same buffer parity.)
// ---------------------------------------------------------------
#define VM_OFF 0
#define XT_OFF 55296
#define PM_SMEM (55296 + 2*18432)

__global__ __launch_bounds__(256)
void k_pm(const float* __restrict__ x, const float* __restrict__ wmix) {
    extern __shared__ __align__(16) char dyn[];
    __half* vm = (__half*)(dyn + VM_OFF);     // 3 planes of 9216 halves
    uint32* Xs = (uint32*)(dyn + XT_OFF);     // 2 buffers of 4608 u32

    int tid = threadIdx.x;
    int hh = blockIdx.x, b = blockIdx.y;
    int lane = tid & 31, wid = tid >> 5;
    int gid = lane >> 2, tig = lane & 3;

    // ---- stage: load 5 x rows, build 3 vertical-max planes (fp16)
    const float* xb = x + (size_t)b*CC*HH*WW;
#pragma unroll
    for (int it = 0; it < 9; it++) {
        int e = tid + it*256;                 // 2304 float4 chunks (64ch x 36)
        int c = e / 36, c4 = e % 36;
        float4 xv[5];
#pragma unroll
        for (int r = 0; r < 5; r++) {
            int y = 3*hh - 1 + r;
            if (y >= 0 && y < HH) xv[r] = *(const float4*)&xb[((size_t)c*HH + y)*WW + c4*4];
            else xv[r] = make_float4(-INFINITY,-INFINITY,-INFINITY,-INFINITY);
        }
#pragma unroll
        for (int i = 0; i < 3; i++) {
            float4 m;
            m.x = fmaxf(fmaxf(xv[i].x, xv[i+1].x), xv[i+2].x);
            m.y = fmaxf(fmaxf(xv[i].y, xv[i+1].y), xv[i+2].y);
            m.z = fmaxf(fmaxf(xv[i].z, xv[i+1].z), xv[i+2].z);
            m.w = fmaxf(fmaxf(xv[i].w, xv[i+1].w), xv[i+2].w);
            __half2 h0 = __floats2half2_rn(m.x, m.y);
            __half2 h1 = __floats2half2_rn(m.z, m.w);
            uint2 st; st.x = *(uint32*)&h0; st.y = *(uint32*)&h1;
            *(uint2*)&vm[i*9216 + c*144 + c4*4] = st;
        }
    }
    __syncthreads();   // vm ready for all groups

    int o0 = (wid >> 1) * 16;
    int pbase = (wid & 1) * 24;

#pragma unroll 1
    for (int g = 0; g < G9; g++) {
        int i = g / 3, j = g - i*3;
        uint32* Xb = Xs + (g & 1) * 4608;
        // ---- build Xs[g&1]: horizontal 3-max of vm[i] at col 3ww+j
        const __half* vmp = vm + i*9216;
#pragma unroll
        for (int it = 0; it < 12; it++) {
            int e = tid + it*256;             // 64*48
            int c = e / 48, ww = e % 48;
            int col = 3*ww + j;
            __half m = vmp[c*144 + col];
            if (col > 0)   m = __hmax(m, vmp[c*144 + col - 1]);
            if (col < 143) m = __hmax(m, vmp[c*144 + col + 1]);
            Xb[c*72 + ww] = f2tf32(__half2float(m));
        }
        // ---- A-fragments for group g: straight from global (L2-hot)
        const float* wg = wmix + g*4096;
        uint32 af[8][4];
#pragma unroll
        for (int kk = 0; kk < 8; kk++) {
            int k0 = kk * 8;
            af[kk][0] = f2tf32(wg[(o0 + gid)    *64 + k0 + tig]);
            af[kk][1] = f2tf32(wg[(o0 + gid + 8)*64 + k0 + tig]);
            af[kk][2] = f2tf32(wg[(o0 + gid)    *64 + k0 + tig + 4]);
            af[kk][3] = f2tf32(wg[(o0 + gid + 8)*64 + k0 + tig + 4]);
        }
        __syncthreads();  // Xs[g&1] ready; MMA(g-1) done by all
        // ---- MMA: warp owns 16 channels x 24 px
        float acc[3][4];
#pragma unroll
        for (int nt = 0; nt < 3; nt++)
#pragma unroll
            for (int q = 0; q < 4; q++) acc[nt][q] = 0.f;
#pragma unroll
        for (int kk = 0; kk < 8; kk++) {
            int k0 = kk * 8;
#pragma unroll
            for (int nt = 0; nt < 3; nt++) {
                int p0 = pbase + nt * 8;
                uint32 b0 = Xb[(k0 + tig)    *72 + p0 + gid];
                uint32 b1 = Xb[(k0 + tig + 4)*72 + p0 + gid];
                mma_tf32(acc[nt], af[kk][0], af[kk][1], af[kk][2], af[kk][3], b0, b1);
            }
        }
        // ---- store fp16 + bn1 stats
        __half* outp = g_mixed + ((size_t)b*C9 + g*CC)*HW + hh*wsz;
        int r0 = o0 + gid, r1 = r0 + 8;
        float s0 = 0.f, q0 = 0.f, s1 = 0.f, q1 = 0.f;
#pragma unroll
        for (int nt = 0; nt < 3; nt++) {
            int p = pbase + nt*8 + 2*tig;
            *(__half2*)&outp[(size_t)r0*HW + p] = __floats2half2_rn(acc[nt][0], acc[nt][1]);
            *(__half2*)&outp[(size_t)r1*HW + p] = __floats2half2_rn(acc[nt][2], acc[nt][3]);
            s0 += acc[nt][0] + acc[nt][1];
            q0 += acc[nt][0]*acc[nt][0] + acc[nt][1]*acc[nt][1];
            s1 += acc[nt][2] + acc[nt][3];
            q1 += acc[nt][2]*acc[nt][2] + acc[nt][3]*acc[nt][3];
        }
#pragma unroll
        for (int off = 1; off <= 2; off <<= 1) {
            s0 += __shfl_xor_sync(0xffffffffu, s0, off);
            q0 += __shfl_xor_sync(0xffffffffu, q0, off);
            s1 += __shfl_xor_sync(0xffffffffu, s1, off);
            q1 += __shfl_xor_sync(0xffffffffu, q1, off);
        }
        if (tig == 0) {
            atomicAdd(&g_sum1[g*CC + r0], s0);
            atomicAdd(&g_sq1[g*CC + r0], q0);
            atomicAdd(&g_sum1[g*CC + r1], s1);
            atomicAdd(&g_sq1[g*CC + r1], q1);
        }
    }
}

// ---------------------------------------------------------------
// K3: fused 4-way dwconv, two channels per block packed f32x2.
// Output g_s now fp16.
// ---------------------------------------------------------------
#define TSTR 68
__global__ __launch_bounds__(256, 2)
void k_conv(const float* __restrict__ wh1, const float* __restrict__ wv1,
            const float* __restrict__ wh2, const float* __restrict__ wv2,
            const float* __restrict__ gm,  const float* __restrict__ bm) {
    __shared__ float2 T2[60*TSTR];
    __shared__ float2 sw1[33], sv1[33], sw2[33], sv2[33];
    __shared__ float rs0[8], rq0[8], rs1[8], rq1[8];
    int tid = threadIdx.x;
    int bc = blockIdx.x; int cp = bc & 31; int b = bc >> 5;
    int c0 = cp*2, c1 = c0 + 1;

    float mn0 = g_sum1[c0] / NPIX, mn1 = g_sum1[c1] / NPIX;
    float vr0 = g_sq1[c0] / NPIX - mn0*mn0, vr1 = g_sq1[c1] / NPIX - mn1*mn1;
    float sc0 = gm[c0] * rsqrtf(vr0 + EPSV), sc1 = gm[c1] * rsqrtf(vr1 + EPSV);
    float sh0 = bm[c0] - mn0*sc0,            sh1 = bm[c1] - mn1*sc1;

    const __half* p0 = g_mixed + ((size_t)b*C9 + c0) * HW;
    const __half* p1 = p0 + HW;
    for (int e = tid; e < 60*TSTR; e += 256) {
        int tr = e / TSTR, tc = e % TSTR;
        int r = tr - 6, q = tc - 9;
        float2 v = make_float2(0.f, 0.f);
        if (r >= 0 && r < hs && q >= 0 && q < wsz) {
            v.x = fmaf(__half2float(p0[r*wsz + q]), sc0, sh0);
            v.y = fmaf(__half2float(p1[r*wsz + q]), sc1, sh1);
        }
        T2[e] = v;
    }
    if (tid < 132) {
        int a = tid / 33, j = tid % 33;
        const float* src = (a == 0) ? wh1 : (a == 1) ? wv1 : (a == 2) ? wh2 : wv2;
        float2 w = make_float2(src[c0*33 + j], src[c1*33 + j]);
        if (a == 0) sw1[j] = w; else if (a == 1) sv1[j] = w;
        else if (a == 2) sw2[j] = w; else sv2[j] = w;
    }
    __syncthreads();

    int tx = tid & 15, ty = tid >> 4;
    int i0 = ty*3, j0 = tx*3;
    ull acc[3][3];
#pragma unroll
    for (int a = 0; a < 3; a++)
#pragma unroll
        for (int bq = 0; bq < 3; bq++) acc[a][bq] = 0ull;

#define T2AT(r,q) (*(const ull*)&T2[((r)+6)*TSTR + ((q)+9)])

#pragma unroll
    for (int v = 0; v < 3; v++) {
        ull wr[11];
#pragma unroll
        for (int u = 0; u < 11; u++) wr[u] = *(const ull*)&sw1[u*3 + v];
        int dc = v - 1;
#pragma unroll
        for (int ox = 0; ox < 3; ox++) {
            ull col[13];
#pragma unroll
            for (int t = 0; t < 13; t++) col[t] = T2AT(i0 + t - 5, j0 + ox + dc);
#pragma unroll
            for (int oy = 0; oy < 3; oy++)
#pragma unroll
                for (int u = 0; u < 11; u++)
                    acc[oy][ox] = ffma2(wr[u], col[oy + u], acc[oy][ox]);
        }
    }
#pragma unroll
    for (int u = 0; u < 3; u++) {
        ull wr[11];
#pragma unroll
        for (int v = 0; v < 11; v++) wr[v] = *(const ull*)&sv1[u*11 + v];
        int dr = u - 1;
#pragma unroll
        for (int oy = 0; oy < 3; oy++) {
            ull row[13];
#pragma unroll
            for (int t = 0; t < 13; t++) row[t] = T2AT(i0 + oy + dr, j0 + t - 5);
#pragma unroll
            for (int ox = 0; ox < 3; ox++)
#pragma unroll
                for (int v = 0; v < 11; v++)
                    acc[oy][ox] = ffma2(wr[v], row[ox + v], acc[oy][ox]);
        }
    }
#pragma unroll
    for (int ee = 0; ee < 3; ee++) {
        int e = ee - 1;
        ull wA[11], wB[11];
#pragma unroll
        for (int u = 0; u < 11; u++) wA[u] = *(const ull*)&sw2[u*3 + ee];
#pragma unroll
        for (int v = 0; v < 11; v++) wB[v] = *(const ull*)&sv2[ee*11 + v];
#pragma unroll
        for (int s2 = 0; s2 < 5; s2++) {
            int d = s2 + e;
            ull strip[15];
#pragma unroll
            for (int s = 0; s < 15; s++)
                strip[s] = T2AT(i0 + s - 6, j0 + d + 6 - s);
#pragma unroll
            for (int oy = 0; oy < 3; oy++) {
                int ox = s2 - oy;
                if (ox < 0 || ox > 2) continue;
#pragma unroll
                for (int u = 0; u < 11; u++)
                    acc[oy][ox] = ffma2(wA[u], strip[oy + u + 1], acc[oy][ox]);
#pragma unroll
                for (int v = 0; v < 11; v++)
                    acc[oy][ox] = ffma2(wB[v], strip[oy + e - v + 11], acc[oy][ox]);
            }
        }
    }
#undef T2AT

    __half* sp0 = g_s + ((size_t)b*CC + c0) * HW;
    __half* sp1 = sp0 + HW;
    ull S = 0ull, Q = 0ull;
#pragma unroll
    for (int oy = 0; oy < 3; oy++)
#pragma unroll
        for (int ox = 0; ox < 3; ox++) {
            float v0, v1; unpack2(acc[oy][ox], v0, v1);
            sp0[(i0 + oy)*wsz + j0 + ox] = __float2half(v0);
            sp1[(i0 + oy)*wsz + j0 + ox] = __float2half(v1);
            S = add2(S, acc[oy][ox]);
            Q = ffma2(acc[oy][ox], acc[oy][ox], Q);
        }
    float s0, s1, q0, q1; unpack2(S, s0, s1); unpack2(Q, q0, q1);
#pragma unroll
    for (int off = 16; off > 0; off >>= 1) {
        s0 += __shfl_xor_sync(0xffffffffu, s0, off);
        q0 += __shfl_xor_sync(0xffffffffu, q0, off);
        s1 += __shfl_xor_sync(0xffffffffu, s1, off);
        q1 += __shfl_xor_sync(0xffffffffu, q1, off);
    }
    int lane = tid & 31, wid = tid >> 5;
    if (lane == 0) { rs0[wid] = s0; rq0[wid] = q0; rs1[wid] = s1; rq1[wid] = q1; }
    __syncthreads();
    if (tid == 0) {
        float a0 = 0.f, b0v = 0.f, a1 = 0.f, b1v = 0.f;
#pragma unroll
        for (int w = 0; w < 8; w++) { a0 += rs0[w]; b0v += rq0[w]; a1 += rs1[w]; b1v += rq1[w]; }
        atomicAdd(&g_sum2[c0], a0); atomicAdd(&g_sq2[c0], b0v);
        atomicAdd(&g_sum2[c1], a1); atomicAdd(&g_sq2[c1], b1v);
    }
}

// ---------------------------------------------------------------
// K4: concat + pixel_shuffle3 + sigmoid gate. Barrier-free.
// Thread owns 24 consecutive output px of one row:
//   3 uint4 fp16 att loads + 6 float4 x loads + 6 float4 stores.
// Block 288 thr = 48 rows; grid (3, 64, 16).
// ---------------------------------------------------------------
__global__ __launch_bounds__(288)
void k_final(const float* __restrict__ x, float* __restrict__ out,
             const float* __restrict__ gm, const float* __restrict__ bm,
             const float* __restrict__ gn, const float* __restrict__ bn) {
    __shared__ float ssc[9], ssh[9];
    int c = blockIdx.y, b = blockIdx.z;
    int tid = threadIdx.x;                        // 0..287
    if (tid < 9) {
        int k = c*9 + tid;
        float mean, var, sc, sh;
        if (k < CC) {
            mean = g_sum2[k] / NPIX; var = g_sq2[k] / NPIX - mean*mean;
            sc = gn[k] * rsqrtf(var + EPSV); sh = bn[k] - mean*sc;
        } else {
            mean = g_sum1[k] / NPIX; var = g_sq1[k] / NPIX - mean*mean;
            sc = gm[k] * rsqrtf(var + EPSV); sh = bm[k] - mean*sc;
        }
        ssc[tid] = sc; ssh[tid] = sh;
    }
    __syncthreads();

    int row = blockIdx.x * 48 + tid / 6;          // output row 0..143
    int k2  = tid % 6;                            // 24-px column group
    int r = row % 3, hh = row / 3, ww0 = k2 * 8;
    size_t spix = (size_t)hh*wsz + ww0;

    float sg[3][8];
#pragma unroll
    for (int s = 0; s < 3; s++) {
        int t = r*3 + s;
        int ch = c*9 + t;
        uint4 u;
        if (ch < CC) u = *(const uint4*)&g_s[((size_t)b*CC + ch)*HW + spix];
        else         u = *(const uint4*)&g_mixed[((size_t)b*C9 + ch)*HW + spix];
        const __half2* h = (const __half2*)&u;
        float sc = ssc[t], sh = ssh[t];
#pragma unroll
        for (int q = 0; q < 4; q++) {
            float2 f = __half22float2(h[q]);
            sg[s][2*q]   = 1.f / (1.f + __expf(-fmaf(f.x, sc, sh)));
            sg[s][2*q+1] = 1.f / (1.f + __expf(-fmaf(f.y, sc, sh)));
        }
    }

    const float* xr = x   + ((size_t)(b*CC + c)*HH + row)*WW + k2*24;
    float*       op = out + ((size_t)(b*CC + c)*HH + row)*WW + k2*24;
#pragma unroll
    for (int q = 0; q < 6; q++) {
        float4 xv = *(const float4*)&xr[q*4];
        float4 o;
        o.x = xv.x * sg[(q*4+0)%3][(q*4+0)/3];
        o.y = xv.y * sg[(q*4+1)%3][(q*4+1)/3];
        o.z = xv.z * sg[(q*4+2)%3][(q*4+2)/3];
        o.w = xv.w * sg[(q*4+3)%3][(q*4+3)/3];
        *(float4*)&op[q*4] = o;
    }
}

// ---------------------------------------------------------------
extern "C" void kernel_launch(void* const* d_in, const int* in_sizes, int n_in,
                              void* d_out, int out_size) {
    const float* x       = (const float*)d_in[0];
    const float* w_mixer = (const float*)d_in[1];
    const float* g_mnorm = (const float*)d_in[2];
    const float* b_mnorm = (const float*)d_in[3];
    const float* w_h1    = (const float*)d_in[4];
    const float* w_v1    = (const float*)d_in[5];
    const float* w_h2    = (const float*)d_in[6];
    const float* w_v2    = (const float*)d_in[7];
    const float* g_norm  = (const float*)d_in[8];
    const float* b_norm  = (const float*)d_in[9];

    cudaFuncSetAttribute(k_pm, cudaFuncAttributeMaxDynamicSharedMemorySize, PM_SMEM);

    k_zero<<<1, 576>>>();
    k_pm<<<dim3(48, 16), 256, PM_SMEM>>>(x, w_mixer);
    k_conv<<<BB*32, 256>>>(w_h1, w_v1, w_h2, w_v2, g_mnorm, b_mnorm);
    k_final<<<dim3(3, 64, 16), 288>>>(x, (float*)d_out, g_mnorm, b_mnorm, g_norm, b_norm);
}